// round 1
// baseline (speedup 1.0000x reference)
#include <cuda_runtime.h>
#include <cuda_bf16.h>

#define BATCH 8192
#define TLEN  512
#define NIN   8
#define NH    16

// 4 threads per batch element. Thread g in [0,4) owns hidden units 4g..4g+3.
// Weights live in registers per thread; h is exchanged via width-4 shuffles.
__global__ __launch_bounds__(128) void rnn_scan_kernel(
    const float* __restrict__ x,     // [B, T, 8]
    const float* __restrict__ W_ih,  // [16, 8]
    const float* __restrict__ W_hh,  // [16, 16]
    const float* __restrict__ b_ih,  // [16]
    const float* __restrict__ b_hh,  // [16]
    const float* __restrict__ fc_w,  // [1, 16]
    const float* __restrict__ fc_b,  // [1]
    float* __restrict__ out)         // [B, 1]
{
    const int tid = blockIdx.x * blockDim.x + threadIdx.x;
    const int b   = tid >> 2;   // batch element
    const int g   = tid & 3;    // which 4 hidden units this thread owns

    // ---- load per-thread weight slices into registers ----
    float wih[4][NIN];
    float whh[4][NH];
    float bias2[4];
    float fcw[4];
#pragma unroll
    for (int r = 0; r < 4; r++) {
        const int j = 4 * g + r;
#pragma unroll
        for (int k = 0; k < NIN; k++) wih[r][k] = W_ih[j * NIN + k];
#pragma unroll
        for (int k = 0; k < NH; k++)  whh[r][k] = W_hh[j * NH + k];
        bias2[r] = b_ih[j] + b_hh[j];
        fcw[r]   = fc_w[j];
    }
    const float fcb = fc_b[0];

    float hf[4] = {0.f, 0.f, 0.f, 0.f};

    const float* xb = x + (size_t)b * (TLEN * NIN);

    // prefetch t=0
    float4 xa = *(const float4*)(xb);
    float4 xc = *(const float4*)(xb + 4);

    for (int t = 0; t < TLEN; t++) {
        // current step inputs
        const float xv[8] = {xa.x, xa.y, xa.z, xa.w, xc.x, xc.y, xc.z, xc.w};

        // prefetch next step's x (hides DRAM latency behind this step's FMAs)
        if (t + 1 < TLEN) {
            const float* xn = xb + (t + 1) * NIN;
            xa = *(const float4*)(xn);
            xc = *(const float4*)(xn + 4);
        }

        // gather full previous h (16 values) from the 4-lane group
        float h16[NH];
#pragma unroll
        for (int k = 0; k < NH; k++)
            h16[k] = __shfl_sync(0xffffffffu, hf[k & 3], k >> 2, 4);

#pragma unroll
        for (int r = 0; r < 4; r++) {
            float acc = bias2[r];
#pragma unroll
            for (int k = 0; k < NIN; k++) acc = fmaf(xv[k], wih[r][k], acc);
#pragma unroll
            for (int k = 0; k < NH; k++)  acc = fmaf(h16[k], whh[r][k], acc);
            // tanh(a) = 1 - 2/(exp(2a)+1)   (accurate to ~1e-6, MUFU-based, cheap)
            hf[r] = 1.0f - __fdividef(2.0f, __expf(2.0f * acc) + 1.0f);
        }
    }

    // ---- final projection: out[b] = sum_j h[j]*fc_w[j] + fc_b ----
    float p = hf[0] * fcw[0];
    p = fmaf(hf[1], fcw[1], p);
    p = fmaf(hf[2], fcw[2], p);
    p = fmaf(hf[3], fcw[3], p);
    p += __shfl_xor_sync(0xffffffffu, p, 1, 4);
    p += __shfl_xor_sync(0xffffffffu, p, 2, 4);
    if (g == 0) out[b] = p + fcb;
}

extern "C" void kernel_launch(void* const* d_in, const int* in_sizes, int n_in,
                              void* d_out, int out_size) {
    const float* x    = (const float*)d_in[0];
    const float* W_ih = (const float*)d_in[1];
    const float* W_hh = (const float*)d_in[2];
    const float* b_ih = (const float*)d_in[3];
    const float* b_hh = (const float*)d_in[4];
    const float* fc_w = (const float*)d_in[5];
    const float* fc_b = (const float*)d_in[6];
    float* out = (float*)d_out;

    const int threads = 128;                 // 32 batch elems per CTA
    const int blocks  = (BATCH * 4) / threads;  // 256 CTAs
    rnn_scan_kernel<<<blocks, threads>>>(x, W_ih, W_hh, b_ih, b_hh, fc_w, fc_b, out);
}

// round 3
// speedup vs baseline: 1.1631x; 1.1631x over previous
#include <cuda_runtime.h>
#include <cuda_bf16.h>

#define BATCH 8192
#define TLEN  512
#define NIN   8
#define NH    16

typedef unsigned long long u64;

__device__ __forceinline__ u64 pack2(float lo, float hi) {
    u64 r; asm("mov.b64 %0, {%1, %2};" : "=l"(r) : "f"(lo), "f"(hi)); return r;
}
__device__ __forceinline__ void unpack2(u64 v, float& lo, float& hi) {
    asm("mov.b64 {%0, %1}, %2;" : "=f"(lo), "=f"(hi) : "l"(v));
}
__device__ __forceinline__ u64 fma2(u64 a, u64 b, u64 c) {
    u64 d; asm("fma.rn.f32x2 %0, %1, %2, %3;" : "=l"(d) : "l"(a), "l"(b), "l"(c)); return d;
}
__device__ __forceinline__ u64 mul2(u64 a, u64 b) {
    u64 d; asm("mul.rn.f32x2 %0, %1, %2;" : "=l"(d) : "l"(a), "l"(b)); return d;
}
__device__ __forceinline__ u64 add2(u64 a, u64 b) {
    u64 d; asm("add.rn.f32x2 %0, %1, %2;" : "=l"(d) : "l"(a), "l"(b)); return d;
}
__device__ __forceinline__ float fast_tanh(float a) {
    float e = __expf(2.0f * a);
    return 1.0f - __fdividef(2.0f, e + 1.0f);
}

// 4 threads per batch element; lane g owns hidden rows 4g..4g+3 and the
// k-slice {4g..4g+3} (recurrent) / {2g,2g+1} (input) of the matvecs.
// Each step: every lane computes f32x2-packed partials for ALL 16 rows from
// its own slice, then a 2-round butterfly reduce-scatter (xor 2, xor 1)
// delivers fully-summed rows to their owner. No pre-gather of h needed.
__global__ __launch_bounds__(128) void rnn_scan_kernel(
    const float* __restrict__ x,     // [B, T, 8]
    const float* __restrict__ W_ih,  // [16, 8]
    const float* __restrict__ W_hh,  // [16, 16]
    const float* __restrict__ b_ih,  // [16]
    const float* __restrict__ b_hh,  // [16]
    const float* __restrict__ fc_w,  // [1, 16]
    const float* __restrict__ fc_b,  // [1]
    float* __restrict__ out)         // [B, 1]
{
    const int tid = blockIdx.x * blockDim.x + threadIdx.x;
    const int b   = tid >> 2;
    const int g   = tid & 3;

    // ---- packed weight slices in registers ----
    // whh2[j][r] = {W_hh[2j][4g+r], W_hh[2j+1][4g+r]}   (rows packed in pairs)
    // wih2[j][c] = {W_ih[2j][2g+c], W_ih[2j+1][2g+c]}
    u64 whh2[8][4], wih2[8][2];
#pragma unroll
    for (int j = 0; j < 8; j++) {
#pragma unroll
        for (int r = 0; r < 4; r++)
            whh2[j][r] = pack2(W_hh[(2*j)*NH + 4*g + r], W_hh[(2*j+1)*NH + 4*g + r]);
#pragma unroll
        for (int c = 0; c < 2; c++)
            wih2[j][c] = pack2(W_ih[(2*j)*NIN + 2*g + c], W_ih[(2*j+1)*NIN + 2*g + c]);
    }
    u64 bias2[2];
#pragma unroll
    for (int i = 0; i < 2; i++)
        bias2[i] = pack2(b_ih[4*g + 2*i]     + b_hh[4*g + 2*i],
                         b_ih[4*g + 2*i + 1] + b_hh[4*g + 2*i + 1]);
    float fcw[4];
#pragma unroll
    for (int r = 0; r < 4; r++) fcw[r] = fc_w[4*g + r];
    const float fcb = fc_b[0];

    // h state: scalars + broadcast-duplicated pairs {h,h} used as FMA multiplier
    float hs[4] = {0.f, 0.f, 0.f, 0.f};
    u64 hd[4] = {0ull, 0ull, 0ull, 0ull};

    const bool keepLo1 = (g & 2) == 0;   // round-1: keep rows 0..7
    const bool keepLo2 = (g & 1) == 0;   // round-2: keep lower pair

    const float* xlane = x + (size_t)b * (TLEN * NIN) + 2 * g;  // this lane's 2 inputs

    // double-buffered x prefetch (2 steps ahead)
    float2 xb0 = *(const float2*)(xlane);
    float2 xb1 = *(const float2*)(xlane + NIN);

#define RNN_STEP(XCUR)                                                          \
    {                                                                           \
        const u64 xd0 = pack2((XCUR).x, (XCUR).x);                              \
        const u64 xd1 = pack2((XCUR).y, (XCUR).y);                              \
        u64 acc[8];                                                             \
        _Pragma("unroll")                                                       \
        for (int j = 0; j < 8; j++) {                                           \
            u64 a = mul2(wih2[j][0], xd0);                                      \
            a = fma2(wih2[j][1], xd1, a);                                       \
            a = fma2(whh2[j][0], hd[0], a);                                     \
            a = fma2(whh2[j][1], hd[1], a);                                     \
            a = fma2(whh2[j][2], hd[2], a);                                     \
            a = fma2(whh2[j][3], hd[3], a);                                     \
            acc[j] = a;                                                         \
        }                                                                       \
        /* round 1: xor-2 */                                                    \
        u64 b1[4];                                                              \
        _Pragma("unroll")                                                       \
        for (int i = 0; i < 4; i++) {                                           \
            u64 s = keepLo1 ? acc[4 + i] : acc[i];                              \
            u64 k = keepLo1 ? acc[i]     : acc[4 + i];                          \
            u64 r = __shfl_xor_sync(0xffffffffu, s, 2, 4);                      \
            b1[i] = add2(k, r);                                                 \
        }                                                                       \
        /* round 2: xor-1 */                                                    \
        u64 c2[2];                                                              \
        _Pragma("unroll")                                                       \
        for (int i = 0; i < 2; i++) {                                           \
            u64 s = keepLo2 ? b1[2 + i] : b1[i];                                \
            u64 k = keepLo2 ? b1[i]     : b1[2 + i];                            \
            u64 r = __shfl_xor_sync(0xffffffffu, s, 1, 4);                      \
            c2[i] = add2(k, r);                                                 \
        }                                                                       \
        c2[0] = add2(c2[0], bias2[0]);                                          \
        c2[1] = add2(c2[1], bias2[1]);                                          \
        float a0, a1, a2, a3;                                                   \
        unpack2(c2[0], a0, a1);                                                 \
        unpack2(c2[1], a2, a3);                                                 \
        hs[0] = fast_tanh(a0); hs[1] = fast_tanh(a1);                           \
        hs[2] = fast_tanh(a2); hs[3] = fast_tanh(a3);                           \
        hd[0] = pack2(hs[0], hs[0]); hd[1] = pack2(hs[1], hs[1]);               \
        hd[2] = pack2(hs[2], hs[2]); hd[3] = pack2(hs[3], hs[3]);               \
    }

    for (int t = 0; t < TLEN; t += 2) {
        float2 cur0 = xb0;
        if (t + 2 < TLEN) xb0 = *(const float2*)(xlane + (size_t)(t + 2) * NIN);
        RNN_STEP(cur0);
        float2 cur1 = xb1;
        if (t + 3 < TLEN) xb1 = *(const float2*)(xlane + (size_t)(t + 3) * NIN);
        RNN_STEP(cur1);
    }
#undef RNN_STEP

    // ---- final projection ----
    float p = hs[0] * fcw[0];
    p = fmaf(hs[1], fcw[1], p);
    p = fmaf(hs[2], fcw[2], p);
    p = fmaf(hs[3], fcw[3], p);
    p += __shfl_xor_sync(0xffffffffu, p, 1, 4);
    p += __shfl_xor_sync(0xffffffffu, p, 2, 4);
    if (g == 0) out[b] = p + fcb;
}

extern "C" void kernel_launch(void* const* d_in, const int* in_sizes, int n_in,
                              void* d_out, int out_size) {
    const float* x    = (const float*)d_in[0];
    const float* W_ih = (const float*)d_in[1];
    const float* W_hh = (const float*)d_in[2];
    const float* b_ih = (const float*)d_in[3];
    const float* b_hh = (const float*)d_in[4];
    const float* fc_w = (const float*)d_in[5];
    const float* fc_b = (const float*)d_in[6];
    float* out = (float*)d_out;

    const int threads = 128;
    const int blocks  = (BATCH * 4) / threads;  // 256 CTAs, 32768 threads
    rnn_scan_kernel<<<blocks, threads>>>(x, W_ih, W_hh, b_ih, b_hh, fc_w, fc_b, out);
}

// round 5
// speedup vs baseline: 1.2028x; 1.0342x over previous
#include <cuda_runtime.h>
#include <cuda_bf16.h>

#define BATCH 8192
#define TLEN  512
#define NIN   8
#define NH    16

typedef unsigned long long u64;

__device__ __forceinline__ u64 pack2(float lo, float hi) {
    u64 r; asm("mov.b64 %0, {%1, %2};" : "=l"(r) : "f"(lo), "f"(hi)); return r;
}
__device__ __forceinline__ void unpack2(u64 v, float& lo, float& hi) {
    asm("mov.b64 {%0, %1}, %2;" : "=f"(lo), "=f"(hi) : "l"(v));
}
__device__ __forceinline__ u64 fma2(u64 a, u64 b, u64 c) {
    u64 d; asm("fma.rn.f32x2 %0, %1, %2, %3;" : "=l"(d) : "l"(a), "l"(b), "l"(c)); return d;
}
__device__ __forceinline__ u64 mul2(u64 a, u64 b) {
    u64 d; asm("mul.rn.f32x2 %0, %1, %2;" : "=l"(d) : "l"(a), "l"(b)); return d;
}
__device__ __forceinline__ u64 add2(u64 a, u64 b) {
    u64 d; asm("add.rn.f32x2 %0, %1, %2;" : "=l"(d) : "l"(a), "l"(b)); return d;
}
// accurate compact tanh: 1 - 2*rcp(exp2(2a*log2e)+1); 5 instr, ~44cyc chain
__device__ __forceinline__ float tanh_acc(float a) {
    float e;
    asm("ex2.approx.f32 %0, %1;" : "=f"(e) : "f"(a * 2.8853900817779268f));
    float r;
    asm("rcp.approx.f32 %0, %1;" : "=f"(r) : "f"(e + 1.0f));
    return fmaf(-2.0f, r, 1.0f);
}

// 4 lanes per batch element. Lane g owns hidden rows 4g..4g+3 (h-slice k=4g..4g+3,
// x-slice 2g..2g+1). Rotated local indexing: local pair i <-> global row-pair
// (2g+i)&7, which makes BOTH reduce-scatter rounds use compile-time-uniform
// register indices (no SELs): r1: shfl_xor(acc[4+i],2); r2: shfl(b1[2+i], g-1).
__global__ __launch_bounds__(128) void rnn_scan_kernel(
    const float* __restrict__ x,     // [B, T, 8]
    const float* __restrict__ W_ih,  // [16, 8]
    const float* __restrict__ W_hh,  // [16, 16]
    const float* __restrict__ b_ih,  // [16]
    const float* __restrict__ b_hh,  // [16]
    const float* __restrict__ fc_w,  // [1, 16]
    const float* __restrict__ fc_b,  // [1]
    float* __restrict__ out)         // [B, 1]
{
    const int tid = blockIdx.x * blockDim.x + threadIdx.x;
    const int b   = tid >> 2;
    const int g   = tid & 3;
    const int src2 = (g + 3) & 3;   // round-2 source lane (g-1 mod 4)

    // ---- rotated packed weight slices ----
    // local pair i -> global rows rA=(4g+2i)&15, rA+1
    u64 whh2[8][4], wih2[8][2];
#pragma unroll
    for (int i = 0; i < 8; i++) {
        const int rA = (4 * g + 2 * i) & 15;
        const int rB = rA + 1;
#pragma unroll
        for (int r = 0; r < 4; r++)
            whh2[i][r] = pack2(W_hh[rA * NH + 4 * g + r], W_hh[rB * NH + 4 * g + r]);
#pragma unroll
        for (int c = 0; c < 2; c++)
            wih2[i][c] = pack2(W_ih[rA * NIN + 2 * g + c], W_ih[rB * NIN + 2 * g + c]);
    }
    // bias for own rows 4g..4g+3 as two pairs
    u64 bias2[2];
#pragma unroll
    for (int i = 0; i < 2; i++)
        bias2[i] = pack2(b_ih[4*g + 2*i]     + b_hh[4*g + 2*i],
                         b_ih[4*g + 2*i + 1] + b_hh[4*g + 2*i + 1]);
    float fcw[4];
#pragma unroll
    for (int r = 0; r < 4; r++) fcw[r] = fc_w[4*g + r];
    const float fcb = fc_b[0];

    // h state: dup pairs {h,h} for own 4 h values; scalars for projection
    u64 hd[4] = {0ull, 0ull, 0ull, 0ull};
    float hs[4] = {0.f, 0.f, 0.f, 0.f};

    const float* xlane = x + (size_t)b * (TLEN * NIN) + 2 * g;

    float2 xb0 = *(const float2*)(xlane);
    float2 xb1 = *(const float2*)(xlane + NIN);

#define RNN_STEP(XCUR)                                                          \
    {                                                                           \
        const u64 xd0 = pack2((XCUR).x, (XCUR).x);                              \
        const u64 xd1 = pack2((XCUR).y, (XCUR).y);                              \
        u64 acc[8];                                                             \
        _Pragma("unroll")                                                       \
        for (int i = 0; i < 8; i++) {                                           \
            u64 a = mul2(wih2[i][0], xd0);                                      \
            a = fma2(wih2[i][1], xd1, a);                                       \
            a = fma2(whh2[i][0], hd[0], a);                                     \
            a = fma2(whh2[i][1], hd[1], a);                                     \
            a = fma2(whh2[i][2], hd[2], a);                                     \
            a = fma2(whh2[i][3], hd[3], a);                                     \
            acc[i] = a;                                                         \
        }                                                                       \
        /* round 1: uniform xor-2 exchange, keep local 0..3 */                  \
        u64 b1[4];                                                              \
        _Pragma("unroll")                                                       \
        for (int i = 0; i < 4; i++) {                                           \
            u64 r = __shfl_xor_sync(0xffffffffu, acc[4 + i], 2, 4);             \
            b1[i] = add2(acc[i], r);                                            \
        }                                                                       \
        /* round 2: uniform idx shfl from lane g-1; pre-add bias in shadow */   \
        u64 c2[2];                                                              \
        _Pragma("unroll")                                                       \
        for (int i = 0; i < 2; i++) {                                           \
            u64 r = __shfl_sync(0xffffffffu, b1[2 + i], src2, 4);               \
            u64 t = add2(b1[i], bias2[i]);                                      \
            c2[i] = add2(t, r);                                                 \
        }                                                                       \
        float a0, a1, a2, a3;                                                   \
        unpack2(c2[0], a0, a1);                                                 \
        unpack2(c2[1], a2, a3);                                                 \
        hs[0] = tanh_acc(a0); hs[1] = tanh_acc(a1);                             \
        hs[2] = tanh_acc(a2); hs[3] = tanh_acc(a3);                             \
        hd[0] = pack2(hs[0], hs[0]); hd[1] = pack2(hs[1], hs[1]);               \
        hd[2] = pack2(hs[2], hs[2]); hd[3] = pack2(hs[3], hs[3]);               \
    }

    for (int t = 0; t < TLEN; t += 2) {
        float2 cur0 = xb0;
        if (t + 2 < TLEN) xb0 = *(const float2*)(xlane + (size_t)(t + 2) * NIN);
        RNN_STEP(cur0);
        float2 cur1 = xb1;
        if (t + 3 < TLEN) xb1 = *(const float2*)(xlane + (size_t)(t + 3) * NIN);
        RNN_STEP(cur1);
    }
#undef RNN_STEP

    // ---- final projection: rows 4g..4g+3 live here ----
    float p = hs[0] * fcw[0];
    p = fmaf(hs[1], fcw[1], p);
    p = fmaf(hs[2], fcw[2], p);
    p = fmaf(hs[3], fcw[3], p);
    p += __shfl_xor_sync(0xffffffffu, p, 1, 4);
    p += __shfl_xor_sync(0xffffffffu, p, 2, 4);
    if (g == 0) out[b] = p + fcb;
}

extern "C" void kernel_launch(void* const* d_in, const int* in_sizes, int n_in,
                              void* d_out, int out_size) {
    const float* x    = (const float*)d_in[0];
    const float* W_ih = (const float*)d_in[1];
    const float* W_hh = (const float*)d_in[2];
    const float* b_ih = (const float*)d_in[3];
    const float* b_hh = (const float*)d_in[4];
    const float* fc_w = (const float*)d_in[5];
    const float* fc_b = (const float*)d_in[6];
    float* out = (float*)d_out;

    const int threads = 128;
    const int blocks  = (BATCH * 4) / threads;  // 256 CTAs, 32768 threads
    rnn_scan_kernel<<<blocks, threads>>>(x, W_ih, W_hh, b_ih, b_hh, fc_w, fc_b, out);
}

// round 6
// speedup vs baseline: 1.4241x; 1.1840x over previous
#include <cuda_runtime.h>
#include <cuda_bf16.h>

#define BATCH 8192
#define TLEN  512
#define NIN   8
#define NH    16

typedef unsigned long long u64;

__device__ __forceinline__ u64 pack2(float lo, float hi) {
    u64 r; asm("mov.b64 %0, {%1, %2};" : "=l"(r) : "f"(lo), "f"(hi)); return r;
}
__device__ __forceinline__ void unpack2(u64 v, float& lo, float& hi) {
    asm("mov.b64 {%0, %1}, %2;" : "=f"(lo), "=f"(hi) : "l"(v));
}
__device__ __forceinline__ u64 fma2(u64 a, u64 b, u64 c) {
    u64 d; asm("fma.rn.f32x2 %0, %1, %2, %3;" : "=l"(d) : "l"(a), "l"(b), "l"(c)); return d;
}
__device__ __forceinline__ u64 mul2(u64 a, u64 b) {
    u64 d; asm("mul.rn.f32x2 %0, %1, %2;" : "=l"(d) : "l"(a), "l"(b)); return d;
}
__device__ __forceinline__ u64 add2(u64 a, u64 b) {
    u64 d; asm("add.rn.f32x2 %0, %1, %2;" : "=l"(d) : "l"(a), "l"(b)); return d;
}
// hardware tanh: single MUFU op (~16cyc), max abs err ~2^-11
__device__ __forceinline__ float tanh_hw(float a) {
    float r; asm("tanh.approx.f32 %0, %1;" : "=f"(r) : "f"(a)); return r;
}

// 4 lanes per batch element. Lane g owns hidden rows 4g..4g+3 (h-slice k=4g..4g+3,
// x-slice 2g..2g+1). Rotated local indexing: local pair i <-> global row-pair
// (2g+i)&7, which makes BOTH reduce-scatter rounds use compile-time-uniform
// register indices (no SELs): r1: shfl_xor(acc[4+i],2); r2: shfl(b1[2+i], g-1).
__global__ __launch_bounds__(128) void rnn_scan_kernel(
    const float* __restrict__ x,     // [B, T, 8]
    const float* __restrict__ W_ih,  // [16, 8]
    const float* __restrict__ W_hh,  // [16, 16]
    const float* __restrict__ b_ih,  // [16]
    const float* __restrict__ b_hh,  // [16]
    const float* __restrict__ fc_w,  // [1, 16]
    const float* __restrict__ fc_b,  // [1]
    float* __restrict__ out)         // [B, 1]
{
    const int tid = blockIdx.x * blockDim.x + threadIdx.x;
    const int b   = tid >> 2;
    const int g   = tid & 3;
    const int src2 = (g + 3) & 3;   // round-2 source lane (g-1 mod 4)

    // ---- rotated packed weight slices ----
    // local pair i -> global rows rA=(4g+2i)&15, rA+1
    u64 whh2[8][4], wih2[8][2];
#pragma unroll
    for (int i = 0; i < 8; i++) {
        const int rA = (4 * g + 2 * i) & 15;
        const int rB = rA + 1;
#pragma unroll
        for (int r = 0; r < 4; r++)
            whh2[i][r] = pack2(W_hh[rA * NH + 4 * g + r], W_hh[rB * NH + 4 * g + r]);
#pragma unroll
        for (int c = 0; c < 2; c++)
            wih2[i][c] = pack2(W_ih[rA * NIN + 2 * g + c], W_ih[rB * NIN + 2 * g + c]);
    }
    // bias for own rows 4g..4g+3 as two pairs
    u64 bias2[2];
#pragma unroll
    for (int i = 0; i < 2; i++)
        bias2[i] = pack2(b_ih[4*g + 2*i]     + b_hh[4*g + 2*i],
                         b_ih[4*g + 2*i + 1] + b_hh[4*g + 2*i + 1]);
    float fcw[4];
#pragma unroll
    for (int r = 0; r < 4; r++) fcw[r] = fc_w[4*g + r];
    const float fcb = fc_b[0];

    // h state: dup pairs {h,h} for own 4 h values; scalars for projection
    u64 hd[4] = {0ull, 0ull, 0ull, 0ull};
    float hs[4] = {0.f, 0.f, 0.f, 0.f};

    const float* xlane = x + (size_t)b * (TLEN * NIN) + 2 * g;

    float2 xb0 = *(const float2*)(xlane);
    float2 xb1 = *(const float2*)(xlane + NIN);

#define RNN_STEP(XCUR)                                                          \
    {                                                                           \
        const u64 xd0 = pack2((XCUR).x, (XCUR).x);                              \
        const u64 xd1 = pack2((XCUR).y, (XCUR).y);                              \
        u64 acc[8];                                                             \
        _Pragma("unroll")                                                       \
        for (int i = 0; i < 8; i++) {                                           \
            u64 a = mul2(wih2[i][0], xd0);                                      \
            a = fma2(wih2[i][1], xd1, a);                                       \
            a = fma2(whh2[i][0], hd[0], a);                                     \
            a = fma2(whh2[i][1], hd[1], a);                                     \
            a = fma2(whh2[i][2], hd[2], a);                                     \
            a = fma2(whh2[i][3], hd[3], a);                                     \
            acc[i] = a;                                                         \
        }                                                                       \
        /* round 1: uniform xor-2 exchange, keep local 0..3 */                  \
        u64 b1[4];                                                              \
        _Pragma("unroll")                                                       \
        for (int i = 0; i < 4; i++) {                                           \
            u64 r = __shfl_xor_sync(0xffffffffu, acc[4 + i], 2, 4);             \
            b1[i] = add2(acc[i], r);                                            \
        }                                                                       \
        /* round 2: uniform idx shfl from lane g-1; pre-add bias in shadow */   \
        u64 c2[2];                                                              \
        _Pragma("unroll")                                                       \
        for (int i = 0; i < 2; i++) {                                           \
            u64 r = __shfl_sync(0xffffffffu, b1[2 + i], src2, 4);               \
            u64 t = add2(b1[i], bias2[i]);                                      \
            c2[i] = add2(t, r);                                                 \
        }                                                                       \
        float a0, a1, a2, a3;                                                   \
        unpack2(c2[0], a0, a1);                                                 \
        unpack2(c2[1], a2, a3);                                                 \
        hs[0] = tanh_hw(a0); hs[1] = tanh_hw(a1);                               \
        hs[2] = tanh_hw(a2); hs[3] = tanh_hw(a3);                               \
        hd[0] = pack2(hs[0], hs[0]); hd[1] = pack2(hs[1], hs[1]);               \
        hd[2] = pack2(hs[2], hs[2]); hd[3] = pack2(hs[3], hs[3]);               \
    }

    for (int t = 0; t < TLEN; t += 2) {
        float2 cur0 = xb0;
        if (t + 2 < TLEN) xb0 = *(const float2*)(xlane + (size_t)(t + 2) * NIN);
        RNN_STEP(cur0);
        float2 cur1 = xb1;
        if (t + 3 < TLEN) xb1 = *(const float2*)(xlane + (size_t)(t + 3) * NIN);
        RNN_STEP(cur1);
    }
#undef RNN_STEP

    // ---- final projection: rows 4g..4g+3 live here ----
    float p = hs[0] * fcw[0];
    p = fmaf(hs[1], fcw[1], p);
    p = fmaf(hs[2], fcw[2], p);
    p = fmaf(hs[3], fcw[3], p);
    p += __shfl_xor_sync(0xffffffffu, p, 1, 4);
    p += __shfl_xor_sync(0xffffffffu, p, 2, 4);
    if (g == 0) out[b] = p + fcb;
}

extern "C" void kernel_launch(void* const* d_in, const int* in_sizes, int n_in,
                              void* d_out, int out_size) {
    const float* x    = (const float*)d_in[0];
    const float* W_ih = (const float*)d_in[1];
    const float* W_hh = (const float*)d_in[2];
    const float* b_ih = (const float*)d_in[3];
    const float* b_hh = (const float*)d_in[4];
    const float* fc_w = (const float*)d_in[5];
    const float* fc_b = (const float*)d_in[6];
    float* out = (float*)d_out;

    const int threads = 128;
    const int blocks  = (BATCH * 4) / threads;  // 256 CTAs, 32768 threads
    rnn_scan_kernel<<<blocks, threads>>>(x, W_ih, W_hh, b_ih, b_hh, fc_w, fc_b, out);
}